// round 15
// baseline (speedup 1.0000x reference)
#include <cuda_runtime.h>
#include <math.h>
#include <stdint.h>

// ---------------------------------------------------------------------------
// SpikingYOLO (fp32, bit-exact vs XLA ref — conv chain k=(ky,kx,ic) ic-inner,
// single FMA chain per output, bias post-add, LIF FMA-contracted).
// R15: conv_s2 32-oc blocks (better waves: conv2 96%, conv3 86.5%; fewer regs
//      -> 3 CTAs/SM target); conv1_lif 32x8 tiles for coalesced stores.
// ---------------------------------------------------------------------------

__device__ float g_l1[41943040];   // spikes layer1: [t*4+b][64][128][128]
__device__ float g_l2[20971520];   // layer2 currents->spikes
__device__ float g_l3[10485760];   // layer3 currents
__device__ float g_pool[1048576];  // pooled
__device__ float g_wt2[73728];     // conv2 w as [kk][ic][oc]
__device__ float g_wt3[294912];    // conv3 w as [kk][ic][oc]

// cp.async 4B with zero-fill when pred==false
__device__ __forceinline__ void cp4(void* smem_dst, const void* gsrc, bool pred) {
    unsigned int s = (unsigned int)__cvta_generic_to_shared(smem_dst);
    int sz = pred ? 4 : 0;
    asm volatile("cp.async.ca.shared.global [%0], [%1], 4, %2;\n"
                 :: "r"(s), "l"(gsrc), "r"(sz));
}
__device__ __forceinline__ void cp_commit() {
    asm volatile("cp.async.commit_group;\n");
}
__device__ __forceinline__ void cp_wait0() {
    asm volatile("cp.async.wait_group 0;\n");
}

// packed f32x2 helpers (lane-wise fma.rn — bit-identical to scalar chains)
__device__ __forceinline__ void fma2(unsigned long long& d,
                                     unsigned long long a,
                                     unsigned long long b) {
    asm("fma.rn.f32x2 %0, %1, %2, %0;" : "+l"(d) : "l"(a), "l"(b));
}
__device__ __forceinline__ unsigned long long pack2(float lo, float hi) {
    unsigned long long r;
    asm("mov.b64 %0, {%1, %2};" : "=l"(r) : "f"(lo), "f"(hi));
    return r;
}
__device__ __forceinline__ void unpack2(unsigned long long p, float& lo, float& hi) {
    asm("mov.b64 {%0, %1}, %2;" : "=f"(lo), "=f"(hi) : "l"(p));
}

// ---------------------------------------------------------------------------
// weight transpose: w[oc][ic][3][3] -> wT[kk][ic][oc], kk = ky*3+kx
// ---------------------------------------------------------------------------
__global__ void wtrans_kernel(const float* __restrict__ w, float* __restrict__ wT,
                              int OC, int IC)
{
    int i = blockIdx.x * 256 + threadIdx.x;
    int total = OC * IC * 9;
    if (i >= total) return;
    int oc = i / (IC * 9);
    int r  = i - oc * (IC * 9);
    int ic = r / 9;
    int kk = r - ic * 9;
    wT[(kk * IC + ic) * OC + oc] = w[i];
}

// ---------------------------------------------------------------------------
// FUSED conv1 (2->64, 3x3, s1, p1) + LIF. Input x [4][2][128][128][10].
// Block: 256 threads = 32x8 px tile (warp spans 32 consecutive x ->
// fully coalesced 128B spike stores). Grid (4 x-tiles * 16 y-tiles, 8 ocb, 4 b).
// ---------------------------------------------------------------------------
__global__ void __launch_bounds__(256) conv1_lif_kernel(
    const float* __restrict__ x, const float* __restrict__ w1,
    const float* __restrict__ b1, float* __restrict__ out)
{
    __shared__ float s_in[2][10][34][10];
    __shared__ float s_w[18][8];

    const int b   = blockIdx.z;
    const int ocb = blockIdx.y * 8;
    const int txo = (blockIdx.x & 3) * 32;
    const int tyo = (blockIdx.x >> 2) * 8;
    const int tid = threadIdx.x;

    if (tid < 144) {
        int ocl = tid / 18, k = tid - ocl * 18;
        s_w[k][ocl] = w1[(ocb + ocl) * 18 + k];
    }
    // halo tile: 2 ic x 10 rows x 34 cols, all 10 t
    for (int i = tid; i < 2 * 10 * 34; i += 256) {
        int ic = i / 340;
        int rem = i - ic * 340;
        int r = rem / 34, c = rem - r * 34;
        int gy = tyo - 1 + r, gx = txo - 1 + c;
        float2* sd = (float2*)s_in[ic][r][c];
        if (gy >= 0 && gy < 128 && gx >= 0 && gx < 128) {
            const float2* gp =
                (const float2*)(x + (size_t)(((b * 2 + ic) * 128 + gy) * 128 + gx) * 10);
            #pragma unroll
            for (int q = 0; q < 5; q++) sd[q] = gp[q];
        } else {
            #pragma unroll
            for (int q = 0; q < 5; q++) sd[q] = make_float2(0.f, 0.f);
        }
    }
    __syncthreads();

    const int tx = tid & 31, ty = tid >> 5;
    float acc[8][10];
    #pragma unroll
    for (int j = 0; j < 8; j++)
        #pragma unroll
        for (int t = 0; t < 10; t++) acc[j][t] = 0.f;

    // chain: k ascending in (ky, kx, ic) — ic INNERMOST
    #pragma unroll 1
    for (int ky = 0; ky < 3; ky++) {
        #pragma unroll
        for (int kx = 0; kx < 3; kx++) {
            #pragma unroll
            for (int ic = 0; ic < 2; ic++) {
                float v[10];
                const float2* vp = (const float2*)s_in[ic][ty + ky][tx + kx];
                #pragma unroll
                for (int q = 0; q < 5; q++) {
                    float2 vv = vp[q];
                    v[2 * q] = vv.x; v[2 * q + 1] = vv.y;
                }
                const int k = ic * 9 + ky * 3 + kx;
                #pragma unroll
                for (int j = 0; j < 8; j++) {
                    float wv = s_w[k][j];
                    #pragma unroll
                    for (int t = 0; t < 10; t++)
                        acc[j][t] = __fmaf_rn(v[t], wv, acc[j][t]);
                }
            }
        }
    }

    const float alpha = expf(-0.05f);
    const float beta  = expf(-0.2f);
    const size_t pxo = (size_t)(tyo + ty) * 128 + (txo + tx);
    #pragma unroll
    for (int j = 0; j < 8; j++) {
        float bv = b1[ocb + j];
        float syn = 0.f, mem = 0.f;
        #pragma unroll
        for (int t = 0; t < 10; t++) {
            float cur = __fadd_rn(acc[j][t], bv);
            syn = __fmaf_rn(beta, syn, cur);
            mem = __fmaf_rn(alpha, mem, syn);
            float sp = (mem >= 1.0f) ? 1.0f : 0.0f;
            mem = __fsub_rn(mem, sp);
            out[((size_t)(t * 4 + b) * 64 + ocb + j) * 16384 + pxo] = sp;
        }
    }
}

// ---------------------------------------------------------------------------
// LIF scan, in place (layer 2). Contracted FMA form.
// ---------------------------------------------------------------------------
__global__ void lif_kernel(float* buf, int n_per_t)
{
    int n = blockIdx.x * 256 + threadIdx.x;
    if (n >= n_per_t) return;
    const float alpha = expf(-0.05f);
    const float beta  = expf(-0.2f);
    float syn = 0.f, mem = 0.f;
    #pragma unroll
    for (int t = 0; t < 10; t++) {
        float cur = buf[(size_t)t * n_per_t + n];
        syn = __fmaf_rn(beta, syn, cur);
        mem = __fmaf_rn(alpha, mem, syn);
        float sp = (mem >= 1.0f) ? 1.0f : 0.0f;
        mem = __fsub_rn(mem, sp);
        buf[(size_t)t * n_per_t + n] = sp;
    }
}

__global__ void lif_pool_kernel(const float* __restrict__ buf,
                                float* __restrict__ pool, int n_per_t)
{
    int n = blockIdx.x * 256 + threadIdx.x;
    if (n >= n_per_t) return;
    const float alpha = expf(-0.05f);
    const float beta  = expf(-0.2f);
    float syn = 0.f, mem = 0.f, sum = 0.f;
    #pragma unroll
    for (int t = 0; t < 10; t++) {
        float cur = buf[(size_t)t * n_per_t + n];
        syn = __fmaf_rn(beta, syn, cur);
        mem = __fmaf_rn(alpha, mem, syn);
        float sp = (mem >= 1.0f) ? 1.0f : 0.0f;
        mem = __fsub_rn(mem, sp);
        sum += sp;
    }
    pool[n] = sum / 10.0f;
}

// ---------------------------------------------------------------------------
// Stride-2 3x3 conv, NHWC chain order (kk outer, ic inner ascending).
// 32-oc blocks: acc[4 oc-pairs][4 px] (32 regs) -> 3 CTAs/SM target.
// Per warp-ic: 1 input LDS.128 + 2 weight LDS.128 + 4 packs + 16 fma2.
// wT layout: [kk][ic][oc].
// ---------------------------------------------------------------------------
template<int IC, int OC, int IH>
__global__ void __launch_bounds__(256, 3) conv_s2_nhwc_kernel(
    const float* __restrict__ in, const float* __restrict__ wT,
    const float* __restrict__ bias, float* __restrict__ out)
{
    constexpr int OH = IH / 2;
    constexpr int TX = OH / 16;
    constexpr int NCH = IC / 16;         // 16-ic chunks per kk
    constexpr int NS = 9 * NCH;          // total stages

    __shared__ float s_w[2][16][32];
    __shared__ float s_x[2][16][16][16];  // [buf][ic][oy][ox]

    const int img = blockIdx.z;
    const int ocb = blockIdx.y * 32;
    const int tyo = (blockIdx.x / TX) * 16;
    const int txo = (blockIdx.x % TX) * 16;
    const int tid = threadIdx.x;
    const int ocg = tid >> 6;            // 0..3 (8 oc each)
    const int tpix = tid & 63;
    const int oy = tpix >> 2;            // 0..15 output row
    const int qx = tpix & 3;             // 0..3  quad of 4 consecutive ox

    const int soy = tid >> 4, sox = tid & 15;

    // acc[p][px]: packed pair (oc 2p, oc 2p+1) chains — lane-wise fma.rn
    unsigned long long acc[4][4];
    const unsigned long long z2 = pack2(0.f, 0.f);
    #pragma unroll
    for (int p = 0; p < 4; p++) {
        acc[p][0] = z2; acc[p][1] = z2; acc[p][2] = z2; acc[p][3] = z2;
    }

    auto stage_load = [&](int s, int bsel) {
        int kk  = s / NCH;
        int icc = (s - kk * NCH) * 16;
        int ky = kk / 3, kx = kk - 3 * ky;
        int iy = 2 * (tyo + soy) + ky - 1;
        int ix = 2 * (txo + sox) + kx - 1;
        bool pred = (iy >= 0) && (iy < IH) && (ix >= 0) && (ix < IH);
        const float* g = pred
            ? in + ((size_t)(img * IC + icc) * IH + iy) * IH + ix
            : in;
        float* sd = &s_x[bsel][0][soy][sox];
        #pragma unroll
        for (int i = 0; i < 16; i++)
            cp4(sd + i * 256, g + (size_t)i * (IH * IH), pred);
        // weights: 16 ic x 32 oc = 512 floats, 2 rounds
        #pragma unroll
        for (int i = 0; i < 2; i++) {
            int idx = tid + i * 256;
            int icl = idx >> 5, ocl = idx & 31;
            cp4(&s_w[bsel][icl][ocl],
                wT + (size_t)(kk * IC + icc + icl) * OC + ocb + ocl, true);
        }
        cp_commit();
    };

    stage_load(0, 0);
    cp_wait0();
    __syncthreads();

    #pragma unroll 1
    for (int s = 0; s < NS; s++) {
        const int cb = s & 1;
        if (s + 1 < NS) stage_load(s + 1, (s + 1) & 1);

        #pragma unroll
        for (int ic = 0; ic < 16; ic++) {
            float4 v = *(const float4*)&s_x[cb][ic][oy][qx * 4];
            unsigned long long vv[4];
            vv[0] = pack2(v.x, v.x);
            vv[1] = pack2(v.y, v.y);
            vv[2] = pack2(v.z, v.z);
            vv[3] = pack2(v.w, v.w);
            // weights: 8 oc = 4 pairs = 2 x ulonglong2 (LDS.128 each)
            const ulonglong2* wp = (const ulonglong2*)&s_w[cb][ic][ocg * 8];
            #pragma unroll
            for (int q = 0; q < 2; q++) {
                ulonglong2 w2 = wp[q];
                #pragma unroll
                for (int px = 0; px < 4; px++) {
                    fma2(acc[2 * q + 0][px], w2.x, vv[px]);
                    fma2(acc[2 * q + 1][px], w2.y, vv[px]);
                }
            }
        }

        if (s + 1 < NS) {
            cp_wait0();
            __syncthreads();
        }
    }

    const int orow = tyo + oy;
    const int ocol = txo + qx * 4;
    #pragma unroll
    for (int p = 0; p < 4; p++) {
        float lo[4], hi[4];
        #pragma unroll
        for (int px = 0; px < 4; px++) unpack2(acc[p][px], lo[px], hi[px]);
        int oc0 = ocb + ocg * 8 + 2 * p;
        float bv0 = bias[oc0], bv1 = bias[oc0 + 1];
        float4 r0, r1;
        r0.x = __fadd_rn(lo[0], bv0); r0.y = __fadd_rn(lo[1], bv0);
        r0.z = __fadd_rn(lo[2], bv0); r0.w = __fadd_rn(lo[3], bv0);
        r1.x = __fadd_rn(hi[0], bv1); r1.y = __fadd_rn(hi[1], bv1);
        r1.z = __fadd_rn(hi[2], bv1); r1.w = __fadd_rn(hi[3], bv1);
        float* op0 = out + ((size_t)img * OC + oc0) * (OH * OH);
        *(float4*)&op0[orow * OH + ocol] = r0;
        *(float4*)&op0[(size_t)(OH * OH) + orow * OH + ocol] = r1;
    }
}

// ---------------------------------------------------------------------------
// det conv: 1x1, 256 -> 255, on pooled [4][256][1024]. k = ic ascending.
// ---------------------------------------------------------------------------
__global__ void __launch_bounds__(256) det_kernel(
    const float* __restrict__ pool, const float* __restrict__ wd,
    const float* __restrict__ bd, float* __restrict__ out)
{
    __shared__ float s_a[64][17];
    __shared__ float s_b[16][64];

    const int bz  = blockIdx.z;
    const int ocb = blockIdx.y * 64;
    const int pxb = blockIdx.x * 64;
    const int tid = threadIdx.x;
    const int ol0 = (tid & 15) * 4;
    const int pl0 = (tid >> 4) * 4;

    float acc[4][4];
    #pragma unroll
    for (int i = 0; i < 4; i++)
        #pragma unroll
        for (int j = 0; j < 4; j++) acc[i][j] = 0.f;

    for (int k0 = 0; k0 < 256; k0 += 16) {
        __syncthreads();
        for (int i = tid; i < 1024; i += 256) {
            int oc_l = i >> 4, kk = i & 15;
            int oc = ocb + oc_l;
            s_a[oc_l][kk] = (oc < 255) ? wd[oc * 256 + k0 + kk] : 0.f;
        }
        for (int i = tid; i < 1024; i += 256) {
            int kk = i >> 6, px_l = i & 63;
            s_b[kk][px_l] = pool[((size_t)bz * 256 + k0 + kk) * 1024 + pxb + px_l];
        }
        __syncthreads();
        #pragma unroll
        for (int kk = 0; kk < 16; kk++) {
            float a0 = s_a[ol0 + 0][kk], a1 = s_a[ol0 + 1][kk];
            float a2 = s_a[ol0 + 2][kk], a3 = s_a[ol0 + 3][kk];
            float b0 = s_b[kk][pl0 + 0], b1 = s_b[kk][pl0 + 1];
            float b2 = s_b[kk][pl0 + 2], b3 = s_b[kk][pl0 + 3];
            acc[0][0] = __fmaf_rn(a0, b0, acc[0][0]); acc[0][1] = __fmaf_rn(a0, b1, acc[0][1]);
            acc[0][2] = __fmaf_rn(a0, b2, acc[0][2]); acc[0][3] = __fmaf_rn(a0, b3, acc[0][3]);
            acc[1][0] = __fmaf_rn(a1, b0, acc[1][0]); acc[1][1] = __fmaf_rn(a1, b1, acc[1][1]);
            acc[1][2] = __fmaf_rn(a1, b2, acc[1][2]); acc[1][3] = __fmaf_rn(a1, b3, acc[1][3]);
            acc[2][0] = __fmaf_rn(a2, b0, acc[2][0]); acc[2][1] = __fmaf_rn(a2, b1, acc[2][1]);
            acc[2][2] = __fmaf_rn(a2, b2, acc[2][2]); acc[2][3] = __fmaf_rn(a2, b3, acc[2][3]);
            acc[3][0] = __fmaf_rn(a3, b0, acc[3][0]); acc[3][1] = __fmaf_rn(a3, b1, acc[3][1]);
            acc[3][2] = __fmaf_rn(a3, b2, acc[3][2]); acc[3][3] = __fmaf_rn(a3, b3, acc[3][3]);
        }
    }

    #pragma unroll
    for (int i = 0; i < 4; i++) {
        int oc = ocb + ol0 + i;
        if (oc >= 255) continue;
        float bv = bd[oc];
        #pragma unroll
        for (int j = 0; j < 4; j++)
            out[((size_t)bz * 255 + oc) * 1024 + pxb + pl0 + j] =
                __fadd_rn(acc[i][j], bv);
    }
}

// ---------------------------------------------------------------------------
extern "C" void kernel_launch(void* const* d_in, const int* in_sizes, int n_in,
                              void* d_out, int out_size)
{
    const float* x  = (const float*)d_in[0];
    const float* w1 = (const float*)d_in[1];
    const float* b1 = (const float*)d_in[2];
    const float* w2 = (const float*)d_in[3];
    const float* b2 = (const float*)d_in[4];
    const float* w3 = (const float*)d_in[5];
    const float* b3 = (const float*)d_in[6];
    const float* wd = (const float*)d_in[7];
    const float* bd = (const float*)d_in[8];
    float* out = (float*)d_out;

    float *l1, *l2, *l3, *pl, *wt2, *wt3;
    cudaGetSymbolAddress((void**)&l1, g_l1);
    cudaGetSymbolAddress((void**)&l2, g_l2);
    cudaGetSymbolAddress((void**)&l3, g_l3);
    cudaGetSymbolAddress((void**)&pl, g_pool);
    cudaGetSymbolAddress((void**)&wt2, g_wt2);
    cudaGetSymbolAddress((void**)&wt3, g_wt3);

    wtrans_kernel<<<(73728 + 255) / 256, 256>>>(w2, wt2, 128, 64);
    wtrans_kernel<<<(294912 + 255) / 256, 256>>>(w3, wt3, 256, 128);

    conv1_lif_kernel<<<dim3(64, 8, 4), 256>>>(x, w1, b1, l1);
    // conv2: 64->128, 32-oc blocks -> 2560 CTAs
    conv_s2_nhwc_kernel<64, 128, 128><<<dim3(16, 4, 40), 256>>>(l1, wt2, b2, l2);
    lif_kernel<<<2097152 / 256, 256>>>(l2, 2097152);
    // conv3: 128->256, 32-oc blocks -> 1280 CTAs
    conv_s2_nhwc_kernel<128, 256, 64><<<dim3(4, 8, 40), 256>>>(l2, wt3, b3, l3);
    lif_pool_kernel<<<1048576 / 256, 256>>>(l3, pl, 1048576);
    det_kernel<<<dim3(16, 4, 4), 256>>>(pl, wd, bd, out);
}

// round 16
// speedup vs baseline: 1.0984x; 1.0984x over previous
#include <cuda_runtime.h>
#include <math.h>
#include <stdint.h>

// ---------------------------------------------------------------------------
// SpikingYOLO (fp32, bit-exact vs XLA ref — conv chain k=(ky,kx,ic) ic-inner,
// single FMA chain per output, bias post-add, LIF FMA-contracted).
// R16: conv_s2 keeps 64-oc blocks (no input re-staging) but splits tiles
//      spatially to 8x16 px -> conv2 2560 CTAs (96% waves), conv3 1280
//      (86.5%); smaller acc -> 3 CTAs/SM. conv1_lif keeps coalesced stores.
// ---------------------------------------------------------------------------

__device__ float g_l1[41943040];   // spikes layer1: [t*4+b][64][128][128]
__device__ float g_l2[20971520];   // layer2 currents->spikes
__device__ float g_l3[10485760];   // layer3 currents
__device__ float g_pool[1048576];  // pooled
__device__ float g_wt2[73728];     // conv2 w as [kk][ic][oc]
__device__ float g_wt3[294912];    // conv3 w as [kk][ic][oc]

// cp.async 4B with zero-fill when pred==false
__device__ __forceinline__ void cp4(void* smem_dst, const void* gsrc, bool pred) {
    unsigned int s = (unsigned int)__cvta_generic_to_shared(smem_dst);
    int sz = pred ? 4 : 0;
    asm volatile("cp.async.ca.shared.global [%0], [%1], 4, %2;\n"
                 :: "r"(s), "l"(gsrc), "r"(sz));
}
__device__ __forceinline__ void cp_commit() {
    asm volatile("cp.async.commit_group;\n");
}
__device__ __forceinline__ void cp_wait0() {
    asm volatile("cp.async.wait_group 0;\n");
}

// packed f32x2 helpers (lane-wise fma.rn — bit-identical to scalar chains)
__device__ __forceinline__ void fma2(unsigned long long& d,
                                     unsigned long long a,
                                     unsigned long long b) {
    asm("fma.rn.f32x2 %0, %1, %2, %0;" : "+l"(d) : "l"(a), "l"(b));
}
__device__ __forceinline__ unsigned long long pack2(float lo, float hi) {
    unsigned long long r;
    asm("mov.b64 %0, {%1, %2};" : "=l"(r) : "f"(lo), "f"(hi));
    return r;
}
__device__ __forceinline__ void unpack2(unsigned long long p, float& lo, float& hi) {
    asm("mov.b64 {%0, %1}, %2;" : "=f"(lo), "=f"(hi) : "l"(p));
}

// ---------------------------------------------------------------------------
// weight transpose: w[oc][ic][3][3] -> wT[kk][ic][oc], kk = ky*3+kx
// ---------------------------------------------------------------------------
__global__ void wtrans_kernel(const float* __restrict__ w, float* __restrict__ wT,
                              int OC, int IC)
{
    int i = blockIdx.x * 256 + threadIdx.x;
    int total = OC * IC * 9;
    if (i >= total) return;
    int oc = i / (IC * 9);
    int r  = i - oc * (IC * 9);
    int ic = r / 9;
    int kk = r - ic * 9;
    wT[(kk * IC + ic) * OC + oc] = w[i];
}

// ---------------------------------------------------------------------------
// FUSED conv1 (2->64, 3x3, s1, p1) + LIF. Input x [4][2][128][128][10].
// Block: 256 threads = 32x8 px tile (coalesced 128B spike stores).
// ---------------------------------------------------------------------------
__global__ void __launch_bounds__(256) conv1_lif_kernel(
    const float* __restrict__ x, const float* __restrict__ w1,
    const float* __restrict__ b1, float* __restrict__ out)
{
    __shared__ float s_in[2][10][34][10];
    __shared__ float s_w[18][8];

    const int b   = blockIdx.z;
    const int ocb = blockIdx.y * 8;
    const int txo = (blockIdx.x & 3) * 32;
    const int tyo = (blockIdx.x >> 2) * 8;
    const int tid = threadIdx.x;

    if (tid < 144) {
        int ocl = tid / 18, k = tid - ocl * 18;
        s_w[k][ocl] = w1[(ocb + ocl) * 18 + k];
    }
    for (int i = tid; i < 2 * 10 * 34; i += 256) {
        int ic = i / 340;
        int rem = i - ic * 340;
        int r = rem / 34, c = rem - r * 34;
        int gy = tyo - 1 + r, gx = txo - 1 + c;
        float2* sd = (float2*)s_in[ic][r][c];
        if (gy >= 0 && gy < 128 && gx >= 0 && gx < 128) {
            const float2* gp =
                (const float2*)(x + (size_t)(((b * 2 + ic) * 128 + gy) * 128 + gx) * 10);
            #pragma unroll
            for (int q = 0; q < 5; q++) sd[q] = gp[q];
        } else {
            #pragma unroll
            for (int q = 0; q < 5; q++) sd[q] = make_float2(0.f, 0.f);
        }
    }
    __syncthreads();

    const int tx = tid & 31, ty = tid >> 5;
    float acc[8][10];
    #pragma unroll
    for (int j = 0; j < 8; j++)
        #pragma unroll
        for (int t = 0; t < 10; t++) acc[j][t] = 0.f;

    // chain: k ascending in (ky, kx, ic) — ic INNERMOST
    #pragma unroll 1
    for (int ky = 0; ky < 3; ky++) {
        #pragma unroll
        for (int kx = 0; kx < 3; kx++) {
            #pragma unroll
            for (int ic = 0; ic < 2; ic++) {
                float v[10];
                const float2* vp = (const float2*)s_in[ic][ty + ky][tx + kx];
                #pragma unroll
                for (int q = 0; q < 5; q++) {
                    float2 vv = vp[q];
                    v[2 * q] = vv.x; v[2 * q + 1] = vv.y;
                }
                const int k = ic * 9 + ky * 3 + kx;
                #pragma unroll
                for (int j = 0; j < 8; j++) {
                    float wv = s_w[k][j];
                    #pragma unroll
                    for (int t = 0; t < 10; t++)
                        acc[j][t] = __fmaf_rn(v[t], wv, acc[j][t]);
                }
            }
        }
    }

    const float alpha = expf(-0.05f);
    const float beta  = expf(-0.2f);
    const size_t pxo = (size_t)(tyo + ty) * 128 + (txo + tx);
    #pragma unroll
    for (int j = 0; j < 8; j++) {
        float bv = b1[ocb + j];
        float syn = 0.f, mem = 0.f;
        #pragma unroll
        for (int t = 0; t < 10; t++) {
            float cur = __fadd_rn(acc[j][t], bv);
            syn = __fmaf_rn(beta, syn, cur);
            mem = __fmaf_rn(alpha, mem, syn);
            float sp = (mem >= 1.0f) ? 1.0f : 0.0f;
            mem = __fsub_rn(mem, sp);
            out[((size_t)(t * 4 + b) * 64 + ocb + j) * 16384 + pxo] = sp;
        }
    }
}

// ---------------------------------------------------------------------------
// LIF scan, in place (layer 2). Contracted FMA form.
// ---------------------------------------------------------------------------
__global__ void lif_kernel(float* buf, int n_per_t)
{
    int n = blockIdx.x * 256 + threadIdx.x;
    if (n >= n_per_t) return;
    const float alpha = expf(-0.05f);
    const float beta  = expf(-0.2f);
    float syn = 0.f, mem = 0.f;
    #pragma unroll
    for (int t = 0; t < 10; t++) {
        float cur = buf[(size_t)t * n_per_t + n];
        syn = __fmaf_rn(beta, syn, cur);
        mem = __fmaf_rn(alpha, mem, syn);
        float sp = (mem >= 1.0f) ? 1.0f : 0.0f;
        mem = __fsub_rn(mem, sp);
        buf[(size_t)t * n_per_t + n] = sp;
    }
}

__global__ void lif_pool_kernel(const float* __restrict__ buf,
                                float* __restrict__ pool, int n_per_t)
{
    int n = blockIdx.x * 256 + threadIdx.x;
    if (n >= n_per_t) return;
    const float alpha = expf(-0.05f);
    const float beta  = expf(-0.2f);
    float syn = 0.f, mem = 0.f, sum = 0.f;
    #pragma unroll
    for (int t = 0; t < 10; t++) {
        float cur = buf[(size_t)t * n_per_t + n];
        syn = __fmaf_rn(beta, syn, cur);
        mem = __fmaf_rn(alpha, mem, syn);
        float sp = (mem >= 1.0f) ? 1.0f : 0.0f;
        mem = __fsub_rn(mem, sp);
        sum += sp;
    }
    pool[n] = sum / 10.0f;
}

// ---------------------------------------------------------------------------
// Stride-2 3x3 conv, NHWC chain order (kk outer, ic inner ascending).
// 64-oc blocks, 8x16 px tiles (spatial split: no input re-staging).
// 256 threads: warp = 1 ocg (8 oc, broadcast weights); 32 lanes = 32 px-quads.
// Thread: 4 oc-pairs x 4 px, packed fma.rn.f32x2 (bit-exact lane-wise).
// wT layout: [kk][ic][oc].
// ---------------------------------------------------------------------------
template<int IC, int OC, int IH>
__global__ void __launch_bounds__(256, 3) conv_s2_nhwc_kernel(
    const float* __restrict__ in, const float* __restrict__ wT,
    const float* __restrict__ bias, float* __restrict__ out)
{
    constexpr int OH = IH / 2;
    constexpr int TX = OH / 16;          // col tiles (16 px wide)
    constexpr int NCH = IC / 16;         // 16-ic chunks per kk
    constexpr int NS = 9 * NCH;          // total stages

    __shared__ float s_w[2][16][64];
    __shared__ float s_x[2][16][8][16];   // [buf][ic][oy][ox]

    const int img = blockIdx.z;
    const int ocb = blockIdx.y * 64;
    const int tyo = (blockIdx.x / TX) * 8;
    const int txo = (blockIdx.x % TX) * 16;
    const int tid = threadIdx.x;
    const int ocg = tid >> 5;            // 0..7 (8 oc each) — warp-uniform
    const int lane = tid & 31;
    const int oy = lane >> 2;            // 0..7 output row
    const int qx = lane & 3;             // 0..3 quad of 4 consecutive ox

    // input staging: 128 px x 16 ic; thread covers 8 ics at one px
    const int spx = tid & 127;
    const int soy = spx >> 4, sox = spx & 15;
    const int sic0 = (tid >> 7) * 8;     // 0 or 8

    unsigned long long acc[4][4];
    const unsigned long long z2 = pack2(0.f, 0.f);
    #pragma unroll
    for (int p = 0; p < 4; p++) {
        acc[p][0] = z2; acc[p][1] = z2; acc[p][2] = z2; acc[p][3] = z2;
    }

    auto stage_load = [&](int s, int bsel) {
        int kk  = s / NCH;
        int icc = (s - kk * NCH) * 16;
        int ky = kk / 3, kx = kk - 3 * ky;
        int iy = 2 * (tyo + soy) + ky - 1;
        int ix = 2 * (txo + sox) + kx - 1;
        bool pred = (iy >= 0) && (iy < IH) && (ix >= 0) && (ix < IH);
        const float* g = pred
            ? in + ((size_t)(img * IC + icc + sic0) * IH + iy) * IH + ix
            : in;
        float* sd = &s_x[bsel][sic0][soy][sox];
        #pragma unroll
        for (int i = 0; i < 8; i++)
            cp4(sd + i * 128, g + (size_t)i * (IH * IH), pred);
        // weights: 16 ic x 64 oc = 1024 floats, 4 rounds
        #pragma unroll
        for (int i = 0; i < 4; i++) {
            int idx = tid + i * 256;
            int icl = idx >> 6, ocl = idx & 63;
            cp4(&s_w[bsel][icl][ocl],
                wT + (size_t)(kk * IC + icc + icl) * OC + ocb + ocl, true);
        }
        cp_commit();
    };

    stage_load(0, 0);
    cp_wait0();
    __syncthreads();

    #pragma unroll 1
    for (int s = 0; s < NS; s++) {
        const int cb = s & 1;
        if (s + 1 < NS) stage_load(s + 1, (s + 1) & 1);

        #pragma unroll
        for (int ic = 0; ic < 16; ic++) {
            float4 v = *(const float4*)&s_x[cb][ic][oy][qx * 4];
            unsigned long long vv[4];
            vv[0] = pack2(v.x, v.x);
            vv[1] = pack2(v.y, v.y);
            vv[2] = pack2(v.z, v.z);
            vv[3] = pack2(v.w, v.w);
            // weights: 8 oc = 4 pairs = 2 x ulonglong2 (broadcast per warp)
            const ulonglong2* wp = (const ulonglong2*)&s_w[cb][ic][ocg * 8];
            #pragma unroll
            for (int q = 0; q < 2; q++) {
                ulonglong2 w2 = wp[q];
                #pragma unroll
                for (int px = 0; px < 4; px++) {
                    fma2(acc[2 * q + 0][px], w2.x, vv[px]);
                    fma2(acc[2 * q + 1][px], w2.y, vv[px]);
                }
            }
        }

        if (s + 1 < NS) {
            cp_wait0();
            __syncthreads();
        }
    }

    const int orow = tyo + oy;
    const int ocol = txo + qx * 4;
    #pragma unroll
    for (int p = 0; p < 4; p++) {
        float lo[4], hi[4];
        #pragma unroll
        for (int px = 0; px < 4; px++) unpack2(acc[p][px], lo[px], hi[px]);
        int oc0 = ocb + ocg * 8 + 2 * p;
        float bv0 = bias[oc0], bv1 = bias[oc0 + 1];
        float4 r0, r1;
        r0.x = __fadd_rn(lo[0], bv0); r0.y = __fadd_rn(lo[1], bv0);
        r0.z = __fadd_rn(lo[2], bv0); r0.w = __fadd_rn(lo[3], bv0);
        r1.x = __fadd_rn(hi[0], bv1); r1.y = __fadd_rn(hi[1], bv1);
        r1.z = __fadd_rn(hi[2], bv1); r1.w = __fadd_rn(hi[3], bv1);
        float* op0 = out + ((size_t)img * OC + oc0) * (OH * OH);
        *(float4*)&op0[orow * OH + ocol] = r0;
        *(float4*)&op0[(size_t)(OH * OH) + orow * OH + ocol] = r1;
    }
}

// ---------------------------------------------------------------------------
// det conv: 1x1, 256 -> 255, on pooled [4][256][1024]. k = ic ascending.
// ---------------------------------------------------------------------------
__global__ void __launch_bounds__(256) det_kernel(
    const float* __restrict__ pool, const float* __restrict__ wd,
    const float* __restrict__ bd, float* __restrict__ out)
{
    __shared__ float s_a[64][17];
    __shared__ float s_b[16][64];

    const int bz  = blockIdx.z;
    const int ocb = blockIdx.y * 64;
    const int pxb = blockIdx.x * 64;
    const int tid = threadIdx.x;
    const int ol0 = (tid & 15) * 4;
    const int pl0 = (tid >> 4) * 4;

    float acc[4][4];
    #pragma unroll
    for (int i = 0; i < 4; i++)
        #pragma unroll
        for (int j = 0; j < 4; j++) acc[i][j] = 0.f;

    for (int k0 = 0; k0 < 256; k0 += 16) {
        __syncthreads();
        for (int i = tid; i < 1024; i += 256) {
            int oc_l = i >> 4, kk = i & 15;
            int oc = ocb + oc_l;
            s_a[oc_l][kk] = (oc < 255) ? wd[oc * 256 + k0 + kk] : 0.f;
        }
        for (int i = tid; i < 1024; i += 256) {
            int kk = i >> 6, px_l = i & 63;
            s_b[kk][px_l] = pool[((size_t)bz * 256 + k0 + kk) * 1024 + pxb + px_l];
        }
        __syncthreads();
        #pragma unroll
        for (int kk = 0; kk < 16; kk++) {
            float a0 = s_a[ol0 + 0][kk], a1 = s_a[ol0 + 1][kk];
            float a2 = s_a[ol0 + 2][kk], a3 = s_a[ol0 + 3][kk];
            float b0 = s_b[kk][pl0 + 0], b1 = s_b[kk][pl0 + 1];
            float b2 = s_b[kk][pl0 + 2], b3 = s_b[kk][pl0 + 3];
            acc[0][0] = __fmaf_rn(a0, b0, acc[0][0]); acc[0][1] = __fmaf_rn(a0, b1, acc[0][1]);
            acc[0][2] = __fmaf_rn(a0, b2, acc[0][2]); acc[0][3] = __fmaf_rn(a0, b3, acc[0][3]);
            acc[1][0] = __fmaf_rn(a1, b0, acc[1][0]); acc[1][1] = __fmaf_rn(a1, b1, acc[1][1]);
            acc[1][2] = __fmaf_rn(a1, b2, acc[1][2]); acc[1][3] = __fmaf_rn(a1, b3, acc[1][3]);
            acc[2][0] = __fmaf_rn(a2, b0, acc[2][0]); acc[2][1] = __fmaf_rn(a2, b1, acc[2][1]);
            acc[2][2] = __fmaf_rn(a2, b2, acc[2][2]); acc[2][3] = __fmaf_rn(a2, b3, acc[2][3]);
            acc[3][0] = __fmaf_rn(a3, b0, acc[3][0]); acc[3][1] = __fmaf_rn(a3, b1, acc[3][1]);
            acc[3][2] = __fmaf_rn(a3, b2, acc[3][2]); acc[3][3] = __fmaf_rn(a3, b3, acc[3][3]);
        }
    }

    #pragma unroll
    for (int i = 0; i < 4; i++) {
        int oc = ocb + ol0 + i;
        if (oc >= 255) continue;
        float bv = bd[oc];
        #pragma unroll
        for (int j = 0; j < 4; j++)
            out[((size_t)bz * 255 + oc) * 1024 + pxb + pl0 + j] =
                __fadd_rn(acc[i][j], bv);
    }
}

// ---------------------------------------------------------------------------
extern "C" void kernel_launch(void* const* d_in, const int* in_sizes, int n_in,
                              void* d_out, int out_size)
{
    const float* x  = (const float*)d_in[0];
    const float* w1 = (const float*)d_in[1];
    const float* b1 = (const float*)d_in[2];
    const float* w2 = (const float*)d_in[3];
    const float* b2 = (const float*)d_in[4];
    const float* w3 = (const float*)d_in[5];
    const float* b3 = (const float*)d_in[6];
    const float* wd = (const float*)d_in[7];
    const float* bd = (const float*)d_in[8];
    float* out = (float*)d_out;

    float *l1, *l2, *l3, *pl, *wt2, *wt3;
    cudaGetSymbolAddress((void**)&l1, g_l1);
    cudaGetSymbolAddress((void**)&l2, g_l2);
    cudaGetSymbolAddress((void**)&l3, g_l3);
    cudaGetSymbolAddress((void**)&pl, g_pool);
    cudaGetSymbolAddress((void**)&wt2, g_wt2);
    cudaGetSymbolAddress((void**)&wt3, g_wt3);

    wtrans_kernel<<<(73728 + 255) / 256, 256>>>(w2, wt2, 128, 64);
    wtrans_kernel<<<(294912 + 255) / 256, 256>>>(w3, wt3, 256, 128);

    conv1_lif_kernel<<<dim3(64, 8, 4), 256>>>(x, w1, b1, l1);
    // conv2: 64->128, 8x16 tiles: 8 row-tiles * 4 col-tiles = 32, 2 ocb -> 2560 CTAs
    conv_s2_nhwc_kernel<64, 128, 128><<<dim3(32, 2, 40), 256>>>(l1, wt2, b2, l2);
    lif_kernel<<<2097152 / 256, 256>>>(l2, 2097152);
    // conv3: 128->256, 8x16 tiles: 4 row-tiles * 2 col-tiles = 8, 4 ocb -> 1280 CTAs
    conv_s2_nhwc_kernel<128, 256, 64><<<dim3(8, 4, 40), 256>>>(l2, wt3, b3, l3);
    lif_pool_kernel<<<1048576 / 256, 256>>>(l3, pl, 1048576);
    det_kernel<<<dim3(16, 4, 4), 256>>>(pl, wd, bd, out);
}